// round 1
// baseline (speedup 1.0000x reference)
#include <cuda_runtime.h>
#include <cstdint>

#define NS 512          // number of sites N
#define DLOC 2
#define CHUNK 16        // sites per lane (32 lanes * 16 = 512)
#define WPB 8           // warps (batches) per block
#define THREADS (WPB * 32)

// Precomputed A coefficients: for each site n, 3 (l,r) pairs {(0,0),(0,1),(1,1)},
// each reduced to 3 quadratic-form coefficients: [A00, A01+A10, A11].
__device__ float g_A[NS * 9];

__global__ void prep_A_kernel(const float* __restrict__ mpo) {
    int n = blockIdx.x * blockDim.x + threadIdx.x;
    if (n >= NS) return;
    const float inv = 1.0f / (1.5707963267948966f + 1e-5f); // 1/PI_HALF
    #pragma unroll
    for (int p = 0; p < 3; p++) {
        int l = (p == 2) ? 1 : 0;
        int r = (p == 0) ? 0 : 1;
        const float* m = mpo + n * 16 + l * 8 + r * 4; // mpo[n,l,r,:,:]
        float a00 = atanf(m[0]) * inv;
        float a01 = atanf(m[1]) * inv;
        float a10 = atanf(m[2]) * inv;
        float a11 = atanf(m[3]) * inv;
        g_A[n * 9 + p * 3 + 0] = a00;
        g_A[n * 9 + p * 3 + 1] = a01 + a10;
        g_A[n * 9 + p * 3 + 2] = a11;
    }
}

__global__ void __launch_bounds__(THREADS)
tdvp_kernel(const float* __restrict__ x,
            const float* __restrict__ scale_p,
            float* __restrict__ out,
            int B)
{
    // Transposed A staging: sA[j*512 + k*32 + lane] holds coeff j of site n=lane*16+k.
    // Consecutive lanes -> consecutive banks: conflict-free LDS.
    __shared__ float sA[9 * CHUNK * 32];

    int tid = threadIdx.x;
    for (int i = tid; i < NS * 9; i += THREADS) {
        int n = i / 9, j = i - n * 9;
        sA[(j * CHUNK + (n & 15)) * 32 + (n >> 4)] = g_A[i];
    }
    __syncthreads();

    const int lane = tid & 31;
    const int warp = tid >> 5;
    const int b = blockIdx.x * WPB + warp;
    if (b >= B) return;

    const float scale = *scale_p;
    const float* xb = x + (size_t)b * (NS * DLOC) + lane * (CHUNK * DLOC);
    const int nbase = lane * CHUNK;

    // ---- Pass A: load x, normalize, build per-site upper-tri M = (m00,m01,m11),
    //              and local chunk aggregate (ca,cb,cd) = prod of this lane's 16 M's.
    float M00[CHUNK], M01[CHUNK], M11[CHUNK];
    float ca = 1.f, cb = 0.f, cd = 1.f;
    #pragma unroll
    for (int k = 0; k < CHUNK; k++) {
        float2 xv = reinterpret_cast<const float2*>(xb)[k];
        float s = xv.x * xv.x + xv.y * xv.y;
        float rn = rsqrtf(s);
        float u0 = xv.x * rn, u1 = xv.y * rn;
        float p = u0 * u0, q = u0 * u1, r = u1 * u1;
        const float* cj = &sA[k * 32 + lane];
        float m00 = p * cj[0 * 512] + q * cj[1 * 512] + r * cj[2 * 512];
        float m01 = p * cj[3 * 512] + q * cj[4 * 512] + r * cj[5 * 512];
        float m11 = p * cj[6 * 512] + q * cj[7 * 512] + r * cj[8 * 512];
        M00[k] = m00; M01[k] = m01; M11[k] = m11;
        // aggregate: C = C @ M  (upper-tri compose)
        float na = ca * m00;
        float nb = ca * m01 + cb * m11;
        cd = cd * m11;
        ca = na; cb = nb;
    }

    // ---- Warp-level exclusive PREFIX scan (need row0 = (a,b) only at the end).
    float pa = ca, pb = cb, pd = cd;
    #pragma unroll
    for (int off = 1; off < 32; off <<= 1) {
        float na = __shfl_up_sync(0xffffffffu, pa, off);
        float nb = __shfl_up_sync(0xffffffffu, pb, off);
        float nd = __shfl_up_sync(0xffffffffu, pd, off);
        if (lane >= off) {
            float ta = na * pa;
            float tb = na * pb + nb * pd;
            float td = nd * pd;
            pa = ta; pb = tb; pd = td;
        }
    }
    float ea = __shfl_up_sync(0xffffffffu, pa, 1);
    float eb = __shfl_up_sync(0xffffffffu, pb, 1);
    if (lane == 0) { ea = 1.f; eb = 0.f; }

    // ---- Warp-level exclusive SUFFIX scan (need col1 = (b,d) only at the end).
    float sa = ca, sb2 = cb, sd2 = cd;
    #pragma unroll
    for (int off = 1; off < 32; off <<= 1) {
        float na = __shfl_down_sync(0xffffffffu, sa, off);
        float nb = __shfl_down_sync(0xffffffffu, sb2, off);
        float nd = __shfl_down_sync(0xffffffffu, sd2, off);
        if (lane + off < 32) {
            float ta = sa * na;
            float tb = sa * nb + sb2 * nd;
            float td = sd2 * nd;
            sa = ta; sb2 = tb; sd2 = td;
        }
    }
    float esb = __shfl_down_sync(0xffffffffu, sb2, 1);
    float esd = __shfl_down_sync(0xffffffffu, sd2, 1);
    if (lane == 31) { esb = 0.f; esd = 1.f; }

    // ---- Backward local walk: compute v[n] = M[n] @ R[n] with
    //      R[n] = normalize(S[n+1] col1), R[N-1] = (0,1) exact.
    float v0[CHUNK], v1[CHUNK];
    {
        float Sb = esb, Sd = esd; // S[nbase+16] col1
        #pragma unroll
        for (int k = CHUNK - 1; k >= 0; k--) {
            float R0, R1;
            if (nbase + k == NS - 1) { R0 = 0.f; R1 = 1.f; }
            else {
                float nm = sqrtf(Sb * Sb + Sd * Sd);
                float iv = 1.0f / (nm + 1e-6f);
                R0 = Sb * iv; R1 = Sd * iv;
            }
            v0[k] = M00[k] * R0 + M01[k] * R1;
            v1[k] = M11[k] * R1;
            float nSb = M00[k] * Sb + M01[k] * Sd; // S[n] = M[n] @ S[n+1]
            Sd = M11[k] * Sd;
            Sb = nSb;
        }
    }

    // ---- Forward local walk: L[n] = normalize(P[n-1] row0), L[0]=(1,0) exact;
    //      y[n] = L . v[n]; relu(scale*y); accumulate L1 sum.
    float ra = ea, rb = eb;
    float sum = 0.f;
    #pragma unroll
    for (int k = 0; k < CHUNK; k++) {
        float L0, L1;
        if (nbase + k == 0) { L0 = 1.f; L1 = 0.f; }
        else {
            float nm = sqrtf(ra * ra + rb * rb);
            float iv = 1.0f / (nm + 1e-6f);
            L0 = ra * iv; L1 = rb * iv;
        }
        float y = L0 * v0[k] + L1 * v1[k];
        float o = fmaxf(scale * y, 0.f);
        v0[k] = o;           // reuse v0 as output staging
        sum += o;
        float nra = ra * M00[k];
        rb = ra * M01[k] + rb * M11[k];
        ra = nra;
    }

    // Warp reduction of per-batch L1 norm, then scaled coalesced-ish float4 stores.
    #pragma unroll
    for (int off = 16; off; off >>= 1)
        sum += __shfl_xor_sync(0xffffffffu, sum, off);
    float invs = 1.0f / (sum + 1e-6f);

    float* ob = out + (size_t)b * NS + nbase;
    #pragma unroll
    for (int k = 0; k < CHUNK; k += 4) {
        float4 v;
        v.x = v0[k + 0] * invs;
        v.y = v0[k + 1] * invs;
        v.z = v0[k + 2] * invs;
        v.w = v0[k + 3] * invs;
        *reinterpret_cast<float4*>(ob + k) = v;
    }
}

extern "C" void kernel_launch(void* const* d_in, const int* in_sizes, int n_in,
                              void* d_out, int out_size) {
    const float* x     = (const float*)d_in[0]; // (B, N, 2)
    const float* mpo   = (const float*)d_in[1]; // (N, 2, 2, 2, 2)
    const float* scale = (const float*)d_in[2]; // scalar
    float* out = (float*)d_out;                 // (B, N)

    int B = in_sizes[0] / (NS * DLOC);

    prep_A_kernel<<<(NS + 255) / 256, 256>>>(mpo);
    int blocks = (B + WPB - 1) / WPB;
    tdvp_kernel<<<blocks, THREADS>>>(x, scale, out, B);
}

// round 3
// speedup vs baseline: 2.7740x; 2.7740x over previous
#include <cuda_runtime.h>
#include <cstdint>

#define NS 512          // number of sites N
#define CHUNK 16        // sites per lane (32 lanes * 16 = 512)
#define WPB 4           // warps (batches) per block
#define THREADS (WPB * 32)

// Precomputed A coefficients, transposed layout: g_A[(j*16 + k)*32 + l] holds
// coefficient j (of 9) for site n = l*16 + k. j = pair*3 + {xx, xy+yx, yy}.
__device__ float g_A[NS * 9];

__global__ void prep_A_kernel(const float* __restrict__ mpo) {
    int n = blockIdx.x * blockDim.x + threadIdx.x;
    if (n >= NS) return;
    const float inv = 1.0f / (1.5707963267948966f + 1e-5f); // 1/PI_HALF
    int l = n >> 4, k = n & 15;
    #pragma unroll
    for (int p = 0; p < 3; p++) {
        int li = (p == 2) ? 1 : 0;
        int ri = (p == 0) ? 0 : 1;
        const float* m = mpo + n * 16 + li * 8 + ri * 4; // mpo[n,li,ri,:,:]
        float a00 = atanf(m[0]) * inv;
        float a01 = atanf(m[1]) * inv;
        float a10 = atanf(m[2]) * inv;
        float a11 = atanf(m[3]) * inv;
        g_A[((p * 3 + 0) * CHUNK + k) * 32 + l] = a00;
        g_A[((p * 3 + 1) * CHUNK + k) * 32 + l] = a01 + a10;
        g_A[((p * 3 + 2) * CHUNK + k) * 32 + l] = a11;
    }
}

// Guarded approximate 1/(sqrt(r2)+eps): rsqrt-based, underflow-safe.
__device__ __forceinline__ float inv_norm_eps(float r2) {
    float nm;
    if (r2 > 1e-36f) {
        float ri = rsqrtf(r2);
        nm = r2 * ri;
    } else {
        nm = 0.0f;
    }
    return __fdividef(1.0f, nm + 1e-6f);
}

__global__ void __launch_bounds__(THREADS, 4)
tdvp_kernel(const float* __restrict__ x,
            const float* __restrict__ scale_p,
            float* __restrict__ out,
            int B)
{
    __shared__ float sA[NS * 9];          // 18432 B
    __shared__ float sX[WPB][32 * 32];    // 16384 B, transposed+swizzled x

    int tid = threadIdx.x;
    #pragma unroll 4
    for (int i = tid; i < NS * 9; i += THREADS) sA[i] = g_A[i];
    __syncthreads();

    const int lane = tid & 31;
    const int warp = tid >> 5;
    const int b = blockIdx.x * WPB + warp;
    if (b >= B) return;

    const float scale = __ldg(scale_p);

    // ---- Stage x: coalesced global float4 loads -> transposed swizzled smem.
    // Logical layout: row r = 2k + c (component c of local-site-index k),
    // col l = owner lane. Physical: sx[r*32 + (l ^ (r & 31))].
    // Verified conflict-free for both these stores and the reads below.
    float* sx = sX[warp];
    {
        const float4* xg = reinterpret_cast<const float4*>(x + (size_t)b * (NS * 2));
        #pragma unroll
        for (int it = 0; it < 8; it++) {
            float4 v = xg[it * 32 + lane];
            int n0 = (it * 32 + lane) * 2;     // even site in this float4
            int l0 = n0 >> 4;
            int r0 = (n0 & 15) * 2;            // rows r0..r0+3 (sites n0, n0+1)
            sx[(r0 + 0) * 32 + (l0 ^ ((r0 + 0) & 31))] = v.x;
            sx[(r0 + 1) * 32 + (l0 ^ ((r0 + 1) & 31))] = v.y;
            sx[(r0 + 2) * 32 + (l0 ^ ((r0 + 2) & 31))] = v.z;
            sx[(r0 + 3) * 32 + (l0 ^ ((r0 + 3) & 31))] = v.w;
        }
        __syncwarp();
    }

    const int nbase = lane * CHUNK;

    // ---- Pass A: normalize x, build per-site upper-tri M = (m00,m01,m11),
    //              and local chunk aggregate (ca,cb,cd).
    float M00[CHUNK], M01[CHUNK], M11[CHUNK];
    float ca = 1.f, cb = 0.f, cd = 1.f;
    #pragma unroll
    for (int k = 0; k < CHUNK; k++) {
        const int r0 = 2 * k, r1 = 2 * k + 1;
        float xv0 = sx[r0 * 32 + (lane ^ (r0 & 31))];
        float xv1 = sx[r1 * 32 + (lane ^ (r1 & 31))];
        float s = xv0 * xv0 + xv1 * xv1;
        float rn = rsqrtf(s);
        float u0 = xv0 * rn, u1 = xv1 * rn;
        float p = u0 * u0, q = u0 * u1, r = u1 * u1;
        const float* cj = &sA[k * 32 + lane];
        float m00 = p * cj[0 * 512] + q * cj[1 * 512] + r * cj[2 * 512];
        float m01 = p * cj[3 * 512] + q * cj[4 * 512] + r * cj[5 * 512];
        float m11 = p * cj[6 * 512] + q * cj[7 * 512] + r * cj[8 * 512];
        M00[k] = m00; M01[k] = m01; M11[k] = m11;
        float na = ca * m00;
        float nb = ca * m01 + cb * m11;
        cd = cd * m11;
        ca = na; cb = nb;
    }

    // ---- Warp Kogge-Stone inclusive PREFIX scan of chunk aggregates.
    float pa = ca, pb = cb, pd = cd;
    #pragma unroll
    for (int off = 1; off < 32; off <<= 1) {
        float na = __shfl_up_sync(0xffffffffu, pa, off);
        float nb = __shfl_up_sync(0xffffffffu, pb, off);
        float nd = __shfl_up_sync(0xffffffffu, pd, off);
        if (lane >= off) {
            float ta = na * pa;
            float tb = na * pb + nb * pd;
            float td = nd * pd;
            pa = ta; pb = tb; pd = td;
        }
    }
    float ea = __shfl_up_sync(0xffffffffu, pa, 1);
    float eb = __shfl_up_sync(0xffffffffu, pb, 1);
    if (lane == 0) { ea = 1.f; eb = 0.f; }

    // ---- Warp inclusive SUFFIX scan.
    float sa = ca, sb2 = cb, sd2 = cd;
    #pragma unroll
    for (int off = 1; off < 32; off <<= 1) {
        float na = __shfl_down_sync(0xffffffffu, sa, off);
        float nb = __shfl_down_sync(0xffffffffu, sb2, off);
        float nd = __shfl_down_sync(0xffffffffu, sd2, off);
        if (lane + off < 32) {
            float ta = sa * na;
            float tb = sa * nb + sb2 * nd;
            float td = sd2 * nd;
            sa = ta; sb2 = tb; sd2 = td;
        }
    }
    float esb = __shfl_down_sync(0xffffffffu, sb2, 1);
    float esd = __shfl_down_sync(0xffffffffu, sd2, 1);
    if (lane == 31) { esb = 0.f; esd = 1.f; }

    // ---- Backward local walk: v[n] = M[n] @ R[n], R[n] = normalize(S[n+1] col1),
    //      R[N-1] = (0,1) exact.
    float v0[CHUNK], v1[CHUNK];
    {
        float Sb = esb, Sd = esd; // S[nbase+16] col1
        #pragma unroll
        for (int k = CHUNK - 1; k >= 0; k--) {
            float R0, R1;
            if (nbase + k == NS - 1) { R0 = 0.f; R1 = 1.f; }
            else {
                float iv = inv_norm_eps(Sb * Sb + Sd * Sd);
                R0 = Sb * iv; R1 = Sd * iv;
            }
            v0[k] = M00[k] * R0 + M01[k] * R1;
            v1[k] = M11[k] * R1;
            float nSb = M00[k] * Sb + M01[k] * Sd; // S[n] = M[n] @ S[n+1]
            Sd = M11[k] * Sd;
            Sb = nSb;
        }
    }

    // ---- Forward local walk: L[n] = normalize(P[n-1] row0), L[0]=(1,0) exact;
    //      y = L . v; relu(scale*y); accumulate L1 sum.
    float ra = ea, rb = eb;
    float sum = 0.f;
    #pragma unroll
    for (int k = 0; k < CHUNK; k++) {
        float L0, L1;
        if (nbase + k == 0) { L0 = 1.f; L1 = 0.f; }
        else {
            float iv = inv_norm_eps(ra * ra + rb * rb);
            L0 = ra * iv; L1 = rb * iv;
        }
        float y = L0 * v0[k] + L1 * v1[k];
        float o = fmaxf(scale * y, 0.f);
        v0[k] = o;           // reuse as output staging
        sum += o;
        float nra = ra * M00[k];
        rb = ra * M01[k] + rb * M11[k];
        ra = nra;
    }

    // ---- Warp reduce per-batch L1 norm, scaled float4 stores.
    #pragma unroll
    for (int off = 16; off; off >>= 1)
        sum += __shfl_xor_sync(0xffffffffu, sum, off);
    float invs = __fdividef(1.0f, sum + 1e-6f);

    float* ob = out + (size_t)b * NS + nbase;
    #pragma unroll
    for (int k = 0; k < CHUNK; k += 4) {
        float4 v;
        v.x = v0[k + 0] * invs;
        v.y = v0[k + 1] * invs;
        v.z = v0[k + 2] * invs;
        v.w = v0[k + 3] * invs;
        *reinterpret_cast<float4*>(ob + k) = v;
    }
}

extern "C" void kernel_launch(void* const* d_in, const int* in_sizes, int n_in,
                              void* d_out, int out_size) {
    const float* x     = (const float*)d_in[0]; // (B, N, 2)
    const float* mpo   = (const float*)d_in[1]; // (N, 2, 2, 2, 2)
    const float* scale = (const float*)d_in[2]; // scalar
    float* out = (float*)d_out;                 // (B, N)

    int B = in_sizes[0] / (NS * 2);

    prep_A_kernel<<<(NS + 255) / 256, 256>>>(mpo);
    int blocks = (B + WPB - 1) / WPB;
    tdvp_kernel<<<blocks, THREADS>>>(x, scale, out, B);
}

// round 4
// speedup vs baseline: 3.1924x; 1.1508x over previous
#include <cuda_runtime.h>
#include <cstdint>

#define NS 512          // number of sites N
#define CHUNK 16        // sites per lane (32 lanes * 16 = 512)
#define WPB 6           // warps (batches) per block
#define THREADS (WPB * 32)

// A coefficients packed per site as 3 float4 planes (one per upper-tri element
// of M): plane p at g_A4[p*NS + k*32 + l] = (c_xx, c_xy+c_yx, c_yy, 0) for
// site n = l*16 + k.  m_p = px*c.x + qxy*c.y + ryy*c.z.
__device__ float4 g_A4[3 * NS];

__global__ void prep_A_kernel(const float* __restrict__ mpo) {
    int n = blockIdx.x * blockDim.x + threadIdx.x;
    if (n >= NS) return;
    const float inv = 1.0f / (1.5707963267948966f + 1e-5f); // 1/PI_HALF
    int l = n >> 4, k = n & 15;
    int idx = k * 32 + l;
    #pragma unroll
    for (int p = 0; p < 3; p++) {
        int li = (p == 2) ? 1 : 0;
        int ri = (p == 0) ? 0 : 1;
        const float* m = mpo + n * 16 + li * 8 + ri * 4; // mpo[n,li,ri,:,:]
        float a00 = atanf(m[0]) * inv;
        float a01 = atanf(m[1]) * inv;
        float a10 = atanf(m[2]) * inv;
        float a11 = atanf(m[3]) * inv;
        g_A4[p * NS + idx] = make_float4(a00, a01 + a10, a11, 0.f);
    }
}

// ||(a,b)|| via rsqrt, safe when a*a+b*b flushes to 0.
__device__ __forceinline__ float safe_norm(float a, float b) {
    float r2 = fmaf(a, a, b * b);
    float nm = r2 * rsqrtf(r2);
    return (r2 > 0.f) ? nm : 0.f;
}

__global__ void __launch_bounds__(THREADS, 4)
tdvp_kernel(const float* __restrict__ x,
            const float* __restrict__ scale_p,
            float* __restrict__ out,
            int B)
{
    __shared__ float4 sA4[3 * NS];        // 24576 B
    __shared__ float  sX[WPB][32 * 32];   // 24576 B  (total 49152 = 48KB)

    int tid = threadIdx.x;
    #pragma unroll 2
    for (int i = tid; i < 3 * NS; i += THREADS) sA4[i] = g_A4[i];
    __syncthreads();

    const int lane = tid & 31;
    const int warp = tid >> 5;
    const int b = blockIdx.x * WPB + warp;
    if (b >= B) return;

    const float scale = __ldg(scale_p);

    // ---- Stage x: coalesced float4 loads -> transposed swizzled smem.
    // Logical row r = 2k + comp, col = owner lane; phys sx[r*32 + (l ^ (r&31))].
    float* sx = sX[warp];
    {
        const float4* xg = reinterpret_cast<const float4*>(x + (size_t)b * (NS * 2));
        #pragma unroll
        for (int it = 0; it < 8; it++) {
            float4 v = xg[it * 32 + lane];
            int n0 = (it * 32 + lane) * 2;
            int l0 = n0 >> 4;
            int r0 = (n0 & 15) * 2;
            sx[(r0 + 0) * 32 + (l0 ^ ((r0 + 0) & 31))] = v.x;
            sx[(r0 + 1) * 32 + (l0 ^ ((r0 + 1) & 31))] = v.y;
            sx[(r0 + 2) * 32 + (l0 ^ ((r0 + 2) & 31))] = v.z;
            sx[(r0 + 3) * 32 + (l0 ^ ((r0 + 3) & 31))] = v.w;
        }
        __syncwarp();
    }

    const int nbase = lane * CHUNK;

    // ---- Pass A: normalize x, build upper-tri M = (m00,m01,m11) per site,
    //              and lane-local chunk aggregate (ca,cb,cd).
    float M00[CHUNK], M01[CHUNK], M11[CHUNK];
    float ca = 1.f, cb = 0.f, cd = 1.f;
    #pragma unroll
    for (int k = 0; k < CHUNK; k++) {
        const int r0 = 2 * k, r1 = 2 * k + 1;
        float xv0 = sx[r0 * 32 + (lane ^ (r0 & 31))];
        float xv1 = sx[r1 * 32 + (lane ^ (r1 & 31))];
        float rn = rsqrtf(fmaf(xv0, xv0, xv1 * xv1));
        float u0 = xv0 * rn, u1 = xv1 * rn;
        float p = u0 * u0, q = u0 * u1, r = u1 * u1;
        const int ai = k * 32 + lane;
        float4 c0 = sA4[0 * NS + ai];
        float4 c1 = sA4[1 * NS + ai];
        float4 c2 = sA4[2 * NS + ai];
        float m00 = p * c0.x + q * c0.y + r * c0.z;
        float m01 = p * c1.x + q * c1.y + r * c1.z;
        float m11 = p * c2.x + q * c2.y + r * c2.z;
        M00[k] = m00; M01[k] = m01; M11[k] = m11;
        float na = ca * m00;
        float nb = ca * m01 + cb * m11;
        cd = cd * m11;
        ca = na; cb = nb;
    }

    // ---- Warp Kogge-Stone inclusive PREFIX scan of chunk aggregates.
    float pa = ca, pb = cb, pd = cd;
    #pragma unroll
    for (int off = 1; off < 32; off <<= 1) {
        float na = __shfl_up_sync(0xffffffffu, pa, off);
        float nb = __shfl_up_sync(0xffffffffu, pb, off);
        float nd = __shfl_up_sync(0xffffffffu, pd, off);
        if (lane >= off) {
            float ta = na * pa;
            float tb = na * pb + nb * pd;
            float td = nd * pd;
            pa = ta; pb = tb; pd = td;
        }
    }
    // Full-chain product entry T[0,1] (lane 31 inclusive prefix).
    float T01 = __shfl_sync(0xffffffffu, pb, 31);
    float ea = __shfl_up_sync(0xffffffffu, pa, 1);
    float eb = __shfl_up_sync(0xffffffffu, pb, 1);
    if (lane == 0) { ea = 1.f; eb = 0.f; }

    // ---- Warp inclusive SUFFIX scan; exclusive tail (col1 only needed).
    float sa = ca, sb2 = cb, sd2 = cd;
    #pragma unroll
    for (int off = 1; off < 32; off <<= 1) {
        float na = __shfl_down_sync(0xffffffffu, sa, off);
        float nb = __shfl_down_sync(0xffffffffu, sb2, off);
        float nd = __shfl_down_sync(0xffffffffu, sd2, off);
        if (lane + off < 32) {
            float ta = sa * na;
            float tb = sa * nb + sb2 * nd;
            float td = sd2 * nd;
            sa = ta; sb2 = tb; sd2 = td;
        }
    }
    float esb = __shfl_down_sync(0xffffffffu, sb2, 1);
    float esd = __shfl_down_sync(0xffffffffu, sd2, 1);
    if (lane == 31) { esb = 0.f; esd = 1.f; }

    // ---- Backward walk: rn[k] = ||S[n+1] col1|| + eps  (exact 1 at n=N-1).
    float rn[CHUNK];
    {
        float Sb = esb, Sd = esd;
        #pragma unroll
        for (int k = CHUNK - 1; k >= 0; k--) {
            rn[k] = (nbase + k == NS - 1) ? 1.0f : (safe_norm(Sb, Sd) + 1e-6f);
            float nSb = M00[k] * Sb + M01[k] * Sd;
            Sd = M11[k] * Sd;
            Sb = nSb;
        }
    }

    // ---- Forward walk: pn = ||P[n-1] row0|| + eps (exact 1 at n=0);
    //      w[k] = 1/(pn*rn[k]);  y[n] = T01 * w[k].
    float ra = ea, rb = eb;
    float sumw = 0.f;
    #pragma unroll
    for (int k = 0; k < CHUNK; k++) {
        float pn = (nbase + k == 0) ? 1.0f : (safe_norm(ra, rb) + 1e-6f);
        float w = __fdividef(1.0f, pn * rn[k]);
        rn[k] = w;              // reuse as staging
        sumw += w;
        float nra = ra * M00[k];
        rb = ra * M01[k] + rb * M11[k];
        ra = nra;
    }

    // ---- Reduce sum of w; fold relu + L1 normalization into one factor.
    #pragma unroll
    for (int off = 16; off; off >>= 1)
        sumw += __shfl_xor_sync(0xffffffffu, sumw, off);

    // o[n] = relu(scale*T01*w) : sign uniform per batch (w > 0).
    float c = scale * T01;
    float f = (c > 0.f) ? __fdividef(c, fmaf(c, sumw, 1e-6f)) : 0.f;

    float* ob = out + (size_t)b * NS + nbase;
    #pragma unroll
    for (int k = 0; k < CHUNK; k += 4) {
        float4 v;
        v.x = rn[k + 0] * f;
        v.y = rn[k + 1] * f;
        v.z = rn[k + 2] * f;
        v.w = rn[k + 3] * f;
        *reinterpret_cast<float4*>(ob + k) = v;
    }
}

extern "C" void kernel_launch(void* const* d_in, const int* in_sizes, int n_in,
                              void* d_out, int out_size) {
    const float* x     = (const float*)d_in[0]; // (B, N, 2)
    const float* mpo   = (const float*)d_in[1]; // (N, 2, 2, 2, 2)
    const float* scale = (const float*)d_in[2]; // scalar
    float* out = (float*)d_out;                 // (B, N)

    int B = in_sizes[0] / (NS * 2);

    prep_A_kernel<<<(NS + 255) / 256, 256>>>(mpo);
    int blocks = (B + WPB - 1) / WPB;
    tdvp_kernel<<<blocks, THREADS>>>(x, scale, out, B);
}